// round 7
// baseline (speedup 1.0000x reference)
#include <cuda_runtime.h>

#define NN 50000
#define EE 800000
#define LATD 64

// ---------------- scratch (static device memory; no allocations) ----------------
__device__ int   g_deg[NN];
__device__ int   g_rowptr[NN + 1];
__device__ int   g_cursor[NN];
__device__ int   g_col[EE];
__device__ float g_invdeg[NN];
__device__ float g_agg[NN * 128];   // layer0 agg, layer1 agg m, layer2 PR m
__device__ float g_aggv[NN * 128];  // layer1 agg v, layer2 PR v
__device__ float g_h1m[NN * 128];
__device__ float g_h1v[NN * 128];
__device__ float g_h2m[NN * 128];
__device__ float g_h2v[NN * 128];
__device__ float g_xtf[NN * 64];        // tf32-rounded x
__device__ float g_wtf[2 * 65536];      // tf32-rounded packed weights (per tower 65536)

__device__ __forceinline__ unsigned f2tf(float f) {
    unsigned u;
    asm("cvt.rna.tf32.f32 %0, %1;" : "=r"(u) : "f"(f));
    return u;
}
__device__ __forceinline__ float f2tff(float f) { return __uint_as_float(f2tf(f)); }

// ---------------- tf32 pre-conversion ----------------
__global__ void k_cvt_x(const float* __restrict__ x) {
    int i = blockIdx.x * blockDim.x + threadIdx.x;  // float4 index
    if (i < NN * 64 / 4) {
        float4 v = *(const float4*)(x + i * 4);
        float4 o;
        o.x = f2tff(v.x); o.y = f2tff(v.y); o.z = f2tff(v.z); o.w = f2tff(v.w);
        *(float4*)(g_xtf + i * 4) = o;
    }
}

struct WPack { const float* p[12]; };  // Wl0,Wr0,Wl1,Wr1,Wl2,Wr2 (m), then (v)

__global__ void k_cvt_w(WPack wp) {
    int i = blockIdx.x * blockDim.x + threadIdx.x;  // float4 index over 131072 floats
    if (i >= 131072 / 4) return;
    int f = i * 4;
    int t = f >> 16;          // tower
    int o = f & 65535;        // offset in tower
    int seg, rel;
    if (o < 8192)        { seg = 0; rel = o; }
    else if (o < 16384)  { seg = 1; rel = o - 8192; }
    else if (o < 32768)  { seg = 2; rel = o - 16384; }
    else if (o < 49152)  { seg = 3; rel = o - 32768; }
    else if (o < 57344)  { seg = 4; rel = o - 49152; }
    else                 { seg = 5; rel = o - 57344; }
    const float* src = wp.p[t * 6 + seg] + rel;
    float4 v = *(const float4*)src;
    float4 w;
    w.x = f2tff(v.x); w.y = f2tff(v.y); w.z = f2tff(v.z); w.w = f2tff(v.w);
    *(float4*)(g_wtf + f) = w;
}

// ---------------- CSR build ----------------
__global__ void k_count(const int* __restrict__ ei) {
    int t = blockIdx.x * blockDim.x + threadIdx.x;
    int e = t * 4;
    if (e < EE) {
        int4 d = *(const int4*)(ei + EE + e);
        atomicAdd(&g_deg[d.x], 1);
        atomicAdd(&g_deg[d.y], 1);
        atomicAdd(&g_deg[d.z], 1);
        atomicAdd(&g_deg[d.w], 1);
    }
}

__global__ void k_scan() {
    __shared__ int wtot[32], wpre[32];
    const int SEG = 1568;
    int tid = threadIdx.x, lane = tid & 31, w = tid >> 5;
    int base = w * SEG;
    int s = 0;
#pragma unroll
    for (int j = 0; j < SEG / 32; j++) {
        int idx = base + j * 32 + lane;
        if (idx < NN) s += g_deg[idx];
    }
#pragma unroll
    for (int o = 16; o; o >>= 1) s += __shfl_xor_sync(0xffffffffu, s, o);
    if (lane == 0) wtot[w] = s;
    __syncthreads();
    if (w == 0) {
        int v = wtot[lane];
        int inc = v;
#pragma unroll
        for (int o = 1; o < 32; o <<= 1) {
            int t = __shfl_up_sync(0xffffffffu, inc, o);
            if (lane >= o) inc += t;
        }
        wpre[lane] = inc - v;
    }
    __syncthreads();
    int run = wpre[w];
#pragma unroll 1
    for (int j = 0; j < SEG / 32; j++) {
        int idx = base + j * 32 + lane;
        int d = (idx < NN) ? g_deg[idx] : 0;
        int inc = d;
#pragma unroll
        for (int o = 1; o < 32; o <<= 1) {
            int t = __shfl_up_sync(0xffffffffu, inc, o);
            if (lane >= o) inc += t;
        }
        if (idx < NN) {
            int off = run + inc - d;
            g_rowptr[idx] = off;
            g_cursor[idx] = off;
            g_invdeg[idx] = 1.0f / fmaxf((float)d, 1.0f);
        }
        run += __shfl_sync(0xffffffffu, inc, 31);
    }
    if (tid == 0) g_rowptr[NN] = EE;
}

__global__ void k_fill(const int* __restrict__ ei) {
    int t = blockIdx.x * blockDim.x + threadIdx.x;
    int e = t * 4;
    if (e < EE) {
        int4 ss = *(const int4*)(ei + e);
        int4 dd = *(const int4*)(ei + EE + e);
        int p;
        p = atomicAdd(&g_cursor[dd.x], 1); g_col[p] = ss.x;
        p = atomicAdd(&g_cursor[dd.y], 1); g_col[p] = ss.y;
        p = atomicAdd(&g_cursor[dd.z], 1); g_col[p] = ss.z;
        p = atomicAdd(&g_cursor[dd.w], 1); g_col[p] = ss.w;
    }
}

// ---------------- SpMM kernels ----------------
// layer 0: agg of x (D=64), 2 nodes per warp (16 lanes x float4), writes tf32
__global__ void k_spmm0(const float* __restrict__ x) {
    int w2 = (blockIdx.x * blockDim.x + threadIdx.x) >> 5;
    int lane = threadIdx.x & 31;
    int node = w2 * 2 + (lane >> 4);
    int l16 = lane & 15;
    if (node >= NN) return;
    int beg = g_rowptr[node], end = g_rowptr[node + 1];
    float4 a0 = make_float4(0.f, 0.f, 0.f, 0.f), a1 = a0, a2 = a0, a3 = a0;
    int e = beg;
    for (; e + 4 <= end; e += 4) {
        int c0 = g_col[e], c1 = g_col[e + 1], c2 = g_col[e + 2], c3 = g_col[e + 3];
        float4 t0 = *(const float4*)(x + (size_t)c0 * 64 + l16 * 4);
        float4 t1 = *(const float4*)(x + (size_t)c1 * 64 + l16 * 4);
        float4 t2 = *(const float4*)(x + (size_t)c2 * 64 + l16 * 4);
        float4 t3 = *(const float4*)(x + (size_t)c3 * 64 + l16 * 4);
        a0.x += t0.x; a0.y += t0.y; a0.z += t0.z; a0.w += t0.w;
        a1.x += t1.x; a1.y += t1.y; a1.z += t1.z; a1.w += t1.w;
        a2.x += t2.x; a2.y += t2.y; a2.z += t2.z; a2.w += t2.w;
        a3.x += t3.x; a3.y += t3.y; a3.z += t3.z; a3.w += t3.w;
    }
    for (; e < end; e++) {
        float4 t = *(const float4*)(x + (size_t)g_col[e] * 64 + l16 * 4);
        a0.x += t.x; a0.y += t.y; a0.z += t.z; a0.w += t.w;
    }
    float sc = g_invdeg[node];
    float4 o;
    o.x = f2tff((a0.x + a1.x + a2.x + a3.x) * sc);
    o.y = f2tff((a0.y + a1.y + a2.y + a3.y) * sc);
    o.z = f2tff((a0.z + a1.z + a2.z + a3.z) * sc);
    o.w = f2tff((a0.w + a1.w + a2.w + a3.w) * sc);
    *(float4*)(g_agg + (size_t)node * 64 + l16 * 4) = o;
}

// layer 1: dual-tower agg of h1m/h1v (D=128), warp per node, unroll 4, writes tf32
__global__ void k_spmm1d(const float* __restrict__ hm, const float* __restrict__ hv) {
    int w = (blockIdx.x * blockDim.x + threadIdx.x) >> 5;
    int lane = threadIdx.x & 31;
    if (w >= NN) return;
    int beg = g_rowptr[w], end = g_rowptr[w + 1];
    float m0 = 0.f, m1 = 0.f, m2 = 0.f, m3 = 0.f;
    float v0 = 0.f, v1 = 0.f, v2 = 0.f, v3 = 0.f;
    int e = beg;
    for (; e + 4 <= end; e += 4) {
        int c0 = g_col[e], c1 = g_col[e + 1], c2 = g_col[e + 2], c3 = g_col[e + 3];
        float4 tm0 = *(const float4*)(hm + (size_t)c0 * 128 + lane * 4);
        float4 tv0 = *(const float4*)(hv + (size_t)c0 * 128 + lane * 4);
        float4 tm1 = *(const float4*)(hm + (size_t)c1 * 128 + lane * 4);
        float4 tv1 = *(const float4*)(hv + (size_t)c1 * 128 + lane * 4);
        float4 tm2 = *(const float4*)(hm + (size_t)c2 * 128 + lane * 4);
        float4 tv2 = *(const float4*)(hv + (size_t)c2 * 128 + lane * 4);
        float4 tm3 = *(const float4*)(hm + (size_t)c3 * 128 + lane * 4);
        float4 tv3 = *(const float4*)(hv + (size_t)c3 * 128 + lane * 4);
        m0 += tm0.x + tm1.x + tm2.x + tm3.x;
        m1 += tm0.y + tm1.y + tm2.y + tm3.y;
        m2 += tm0.z + tm1.z + tm2.z + tm3.z;
        m3 += tm0.w + tm1.w + tm2.w + tm3.w;
        v0 += tv0.x + tv1.x + tv2.x + tv3.x;
        v1 += tv0.y + tv1.y + tv2.y + tv3.y;
        v2 += tv0.z + tv1.z + tv2.z + tv3.z;
        v3 += tv0.w + tv1.w + tv2.w + tv3.w;
    }
    for (; e < end; e++) {
        int c0 = g_col[e];
        float4 tm = *(const float4*)(hm + (size_t)c0 * 128 + lane * 4);
        float4 tv = *(const float4*)(hv + (size_t)c0 * 128 + lane * 4);
        m0 += tm.x; m1 += tm.y; m2 += tm.z; m3 += tm.w;
        v0 += tv.x; v1 += tv.y; v2 += tv.z; v3 += tv.w;
    }
    float sc = g_invdeg[w];
    float4 om, ov;
    om.x = f2tff(m0 * sc); om.y = f2tff(m1 * sc); om.z = f2tff(m2 * sc); om.w = f2tff(m3 * sc);
    ov.x = f2tff(v0 * sc); ov.y = f2tff(v1 * sc); ov.z = f2tff(v2 * sc); ov.w = f2tff(v3 * sc);
    *(float4*)(g_agg + (size_t)w * 128 + lane * 4) = om;
    *(float4*)(g_aggv + (size_t)w * 128 + lane * 4) = ov;
}

// layer 2: out = S*P + R; PR rows = [P(64) | R(64)]; 2 nodes/warp, writes d_out (fp32)
__global__ void k_spmm2d(const float* __restrict__ PRm, const float* __restrict__ PRv,
                         float* __restrict__ outm, float* __restrict__ outv) {
    int w2 = (blockIdx.x * blockDim.x + threadIdx.x) >> 5;
    int lane = threadIdx.x & 31;
    int node = w2 * 2 + (lane >> 4);
    int l16 = lane & 15;
    if (node >= NN) return;
    int beg = g_rowptr[node], end = g_rowptr[node + 1];
    float m0 = 0.f, m1 = 0.f, m2 = 0.f, m3 = 0.f;
    float v0 = 0.f, v1 = 0.f, v2 = 0.f, v3 = 0.f;
    int e = beg;
    for (; e + 2 <= end; e += 2) {
        int c0 = g_col[e], c1 = g_col[e + 1];
        float4 tm0 = *(const float4*)(PRm + (size_t)c0 * 128 + l16 * 4);
        float4 tv0 = *(const float4*)(PRv + (size_t)c0 * 128 + l16 * 4);
        float4 tm1 = *(const float4*)(PRm + (size_t)c1 * 128 + l16 * 4);
        float4 tv1 = *(const float4*)(PRv + (size_t)c1 * 128 + l16 * 4);
        m0 += tm0.x + tm1.x; m1 += tm0.y + tm1.y; m2 += tm0.z + tm1.z; m3 += tm0.w + tm1.w;
        v0 += tv0.x + tv1.x; v1 += tv0.y + tv1.y; v2 += tv0.z + tv1.z; v3 += tv0.w + tv1.w;
    }
    for (; e < end; e++) {
        int c0 = g_col[e];
        float4 tm = *(const float4*)(PRm + (size_t)c0 * 128 + l16 * 4);
        float4 tv = *(const float4*)(PRv + (size_t)c0 * 128 + l16 * 4);
        m0 += tm.x; m1 += tm.y; m2 += tm.z; m3 += tm.w;
        v0 += tv.x; v1 += tv.y; v2 += tv.z; v3 += tv.w;
    }
    float sc = g_invdeg[node];
    float4 rm = *(const float4*)(PRm + (size_t)node * 128 + 64 + l16 * 4);
    float4 rv = *(const float4*)(PRv + (size_t)node * 128 + 64 + l16 * 4);
    float4 om, ov;
    om.x = m0 * sc + rm.x; om.y = m1 * sc + rm.y; om.z = m2 * sc + rm.z; om.w = m3 * sc + rm.w;
    ov.x = v0 * sc + rv.x; ov.y = v1 * sc + rv.y; ov.z = v2 * sc + rv.z; ov.w = v3 * sc + rv.w;
    *(float4*)(outm + (size_t)node * 64 + l16 * 4) = om;
    *(float4*)(outv + (size_t)node * 64 + l16 * 4) = ov;
}

// ---------------- tf32 tensor-core GEMM (cp.async double-buffered) ----------------
__device__ __forceinline__ void mma8(float* d, const unsigned* a, const unsigned* b) {
    asm volatile(
        "mma.sync.aligned.m16n8k8.row.col.f32.tf32.tf32.f32 "
        "{%0,%1,%2,%3}, {%4,%5,%6,%7}, {%8,%9}, {%0,%1,%2,%3};\n"
        : "+f"(d[0]), "+f"(d[1]), "+f"(d[2]), "+f"(d[3])
        : "r"(a[0]), "r"(a[1]), "r"(a[2]), "r"(a[3]), "r"(b[0]), "r"(b[1]));
}

struct GArgs {
    const float *A0, *A1, *Wa, *Wb, *bias, *gam, *bet;
    float* out;
};

// MODE 0 (LN): out = tf32(LNReLU(A0@Wa^T + bias + A1@Wb^T)), DOUT=128
// MODE 1 (PR): out = [A0@Wa_pack^T(128 cols); bias on cols 64..127]   (raw fp32)
// All A/W inputs are pre-rounded to tf32. Block tile 128x128, 8 warps 4x2, K chunk 64.
template <int DIN, int MODE>
__global__ __launch_bounds__(256) void k_gemm_tc(GArgs am, GArgs av) {
    const GArgs A = blockIdx.y ? av : am;
    constexpr int NT = 8;                       // 128/16 n-tiles per warp
    constexpr int KC = DIN / 64;                // chunks per phase
    constexpr int NC = (MODE == 0 ? 2 : 1) * KC;
    constexpr int STAGE = 2 * 128 * 68;         // unsigneds per stage (A+B)

    extern __shared__ unsigned sh[];
    __shared__ float sS[MODE == 0 ? 256 : 1];
    __shared__ float sQ[MODE == 0 ? 256 : 1];
    __shared__ float sMean[MODE == 0 ? 128 : 1];
    __shared__ float sRstd[MODE == 0 ? 128 : 1];

    const int tid = threadIdx.x;
    const int lane = tid & 31;
    const int warp = tid >> 5;
    const int warpM = warp & 3;
    const int warpN = warp >> 2;
    const int g = lane >> 2;
    const int c = lane & 3;
    const int m0 = blockIdx.x * 128;
    unsigned sbase;
    {
        unsigned long long gp = __cvta_generic_to_shared(sh);
        sbase = (unsigned)gp;
    }

    float acc[2][NT][4];
#pragma unroll
    for (int mi = 0; mi < 2; mi++)
#pragma unroll
        for (int ni = 0; ni < NT; ni++)
#pragma unroll
            for (int r = 0; r < 4; r++) acc[mi][ni][r] = 0.0f;

    auto issue = [&](int i, int s) {
        int ph = (MODE == 0) ? (i / KC) : 0;
        int k0 = (i % KC) * 64;
        const float* Ap = (MODE == 0 && ph) ? A.A1 : A.A0;
        const float* Wp = (MODE == 0 && ph) ? A.Wb : A.Wa;
        unsigned abase = sbase + s * STAGE * 4;
        unsigned bbase = abase + 128 * 68 * 4;
#pragma unroll
        for (int j = 0; j < 8; j++) {
            int idx = tid + j * 256;
            int m = idx >> 4;
            int kq = (idx & 15) * 4;
            int row = m0 + m;
            int rc = row < NN ? row : NN - 1;
            const float* src = Ap + (size_t)rc * DIN + k0 + kq;
            int sz = (row < NN) ? 16 : 0;
            unsigned d = abase + (m * 68 + kq) * 4;
            asm volatile("cp.async.cg.shared.global [%0], [%1], 16, %2;\n" ::"r"(d), "l"(src), "r"(sz));
        }
#pragma unroll
        for (int j = 0; j < 8; j++) {
            int idx = tid + j * 256;
            int n = idx >> 4;
            int kq = (idx & 15) * 4;
            const float* src = Wp + n * DIN + k0 + kq;
            unsigned d = bbase + (n * 68 + kq) * 4;
            asm volatile("cp.async.cg.shared.global [%0], [%1], 16;\n" ::"r"(d), "l"(src));
        }
        asm volatile("cp.async.commit_group;\n");
    };

    issue(0, 0);
#pragma unroll
    for (int i = 0; i < NC; i++) {
        if (i + 1 < NC) {
            issue(i + 1, (i + 1) & 1);
            asm volatile("cp.async.wait_group 1;\n");
        } else {
            asm volatile("cp.async.wait_group 0;\n");
        }
        __syncthreads();
        const unsigned* As = sh + (i & 1) * STAGE;
        const unsigned* Bs = As + 128 * 68;
#pragma unroll
        for (int ks = 0; ks < 8; ks++) {
            int kk = ks * 8;
            unsigned a[2][4];
#pragma unroll
            for (int mi = 0; mi < 2; mi++) {
                int mb = warpM * 32 + mi * 16;
                a[mi][0] = As[(mb + g) * 68 + kk + c];
                a[mi][1] = As[(mb + g + 8) * 68 + kk + c];
                a[mi][2] = As[(mb + g) * 68 + kk + c + 4];
                a[mi][3] = As[(mb + g + 8) * 68 + kk + c + 4];
            }
            unsigned b[NT][2];
#pragma unroll
            for (int ni = 0; ni < NT; ni++) {
                int nb = warpN * 64 + ni * 8;
                b[ni][0] = Bs[(nb + g) * 68 + kk + c];
                b[ni][1] = Bs[(nb + g) * 68 + kk + c + 4];
            }
#pragma unroll
            for (int mi = 0; mi < 2; mi++)
#pragma unroll
                for (int ni = 0; ni < NT; ni++) mma8(acc[mi][ni], a[mi], b[ni]);
        }
        __syncthreads();
    }

    // bias
    if (MODE == 0) {
#pragma unroll
        for (int ni = 0; ni < NT; ni++) {
            int col = warpN * 64 + ni * 8 + 2 * c;
            float b0 = A.bias[col], b1 = A.bias[col + 1];
#pragma unroll
            for (int mi = 0; mi < 2; mi++) {
                acc[mi][ni][0] += b0; acc[mi][ni][1] += b1;
                acc[mi][ni][2] += b0; acc[mi][ni][3] += b1;
            }
        }
    } else if (warpN == 1) {  // bias only on R half (cols 64..127)
#pragma unroll
        for (int ni = 0; ni < NT; ni++) {
            int cl = ni * 8 + 2 * c;
            float b0 = A.bias[cl], b1 = A.bias[cl + 1];
#pragma unroll
            for (int mi = 0; mi < 2; mi++) {
                acc[mi][ni][0] += b0; acc[mi][ni][1] += b1;
                acc[mi][ni][2] += b0; acc[mi][ni][3] += b1;
            }
        }
    }

    if (MODE == 0) {
#pragma unroll
        for (int mi = 0; mi < 2; mi++)
#pragma unroll
            for (int h = 0; h < 2; h++) {
                float s = 0.f, q = 0.f;
#pragma unroll
                for (int ni = 0; ni < NT; ni++) {
                    float u0 = acc[mi][ni][2 * h], u1 = acc[mi][ni][2 * h + 1];
                    s += u0 + u1;
                    q += u0 * u0 + u1 * u1;
                }
                s += __shfl_xor_sync(0xffffffffu, s, 1);
                s += __shfl_xor_sync(0xffffffffu, s, 2);
                q += __shfl_xor_sync(0xffffffffu, q, 1);
                q += __shfl_xor_sync(0xffffffffu, q, 2);
                if (c == 0) {
                    int row = warpM * 32 + mi * 16 + h * 8 + g;
                    sS[row * 2 + warpN] = s;
                    sQ[row * 2 + warpN] = q;
                }
            }
        __syncthreads();
        if (tid < 128) {
            float s = sS[tid * 2] + sS[tid * 2 + 1];
            float q = sQ[tid * 2] + sQ[tid * 2 + 1];
            float mean = s * (1.0f / 128);
            float var = q * (1.0f / 128) - mean * mean;
            sMean[tid] = mean;
            sRstd[tid] = rsqrtf(var + 1e-5f);
        }
        __syncthreads();
#pragma unroll
        for (int mi = 0; mi < 2; mi++)
#pragma unroll
            for (int h = 0; h < 2; h++) {
                int row = warpM * 32 + mi * 16 + h * 8 + g;
                int n = m0 + row;
                if (n < NN) {
                    float mean = sMean[row], rs = sRstd[row];
#pragma unroll
                    for (int ni = 0; ni < NT; ni++) {
                        int col = warpN * 64 + ni * 8 + 2 * c;
                        float u0 = (acc[mi][ni][2 * h] - mean) * rs * A.gam[col] + A.bet[col];
                        float u1 = (acc[mi][ni][2 * h + 1] - mean) * rs * A.gam[col + 1] + A.bet[col + 1];
                        float2 o;
                        o.x = f2tff(fmaxf(u0, 0.0f));
                        o.y = f2tff(fmaxf(u1, 0.0f));
                        *(float2*)(A.out + (size_t)n * 128 + col) = o;
                    }
                }
            }
    } else {
#pragma unroll
        for (int mi = 0; mi < 2; mi++)
#pragma unroll
            for (int h = 0; h < 2; h++) {
                int row = warpM * 32 + mi * 16 + h * 8 + g;
                int n = m0 + row;
                if (n < NN) {
#pragma unroll
                    for (int ni = 0; ni < NT; ni++) {
                        int col = warpN * 64 + ni * 8 + 2 * c;
                        float2 o;
                        o.x = acc[mi][ni][2 * h];
                        o.y = acc[mi][ni][2 * h + 1];
                        *(float2*)(A.out + (size_t)n * 128 + col) = o;
                    }
                }
            }
    }
}

// ---------------- launch ----------------
extern "C" void kernel_launch(void* const* d_in, const int* in_sizes, int n_in,
                              void* d_out, int out_size) {
    const float* x = (const float*)d_in[0];
    const int* ei = (const int*)d_in[1];
    const float* W[26];
    for (int i = 0; i < 26; i++) W[i] = (const float*)d_in[2 + i];
    // m: Wl0=0 bl0=1 Wr0=2 g0=3 b0=4 | Wl1=5 bl1=6 Wr1=7 g1=8 b1=9 | Wl2=10 bl2=11 Wr2=12; v=+13

    float *agg, *aggv, *h1m, *h1v, *h2m, *h2v, *xtf, *wtf;
    int* degp;
    cudaGetSymbolAddress((void**)&agg, g_agg);
    cudaGetSymbolAddress((void**)&aggv, g_aggv);
    cudaGetSymbolAddress((void**)&h1m, g_h1m);
    cudaGetSymbolAddress((void**)&h1v, g_h1v);
    cudaGetSymbolAddress((void**)&h2m, g_h2m);
    cudaGetSymbolAddress((void**)&h2v, g_h2v);
    cudaGetSymbolAddress((void**)&xtf, g_xtf);
    cudaGetSymbolAddress((void**)&wtf, g_wtf);
    cudaGetSymbolAddress((void**)&degp, g_deg);

    float* out_mu = (float*)d_out;
    float* out_lv = out_mu + (size_t)NN * LATD;

    const int SMEM = 2 * 2 * 128 * 68 * 4;  // 139264 bytes (2 stages x (A+B))
    cudaFuncSetAttribute(k_gemm_tc<64, 0>, cudaFuncAttributeMaxDynamicSharedMemorySize, SMEM);
    cudaFuncSetAttribute(k_gemm_tc<128, 0>, cudaFuncAttributeMaxDynamicSharedMemorySize, SMEM);
    cudaFuncSetAttribute(k_gemm_tc<128, 1>, cudaFuncAttributeMaxDynamicSharedMemorySize, SMEM);

    // tf32 pre-conversion
    k_cvt_x<<<(NN * 64 / 4 + 255) / 256, 256>>>(x);
    {
        WPack wp;
        wp.p[0] = W[0];  wp.p[1] = W[2];  wp.p[2] = W[5];  wp.p[3] = W[7];
        wp.p[4] = W[10]; wp.p[5] = W[12];
        wp.p[6] = W[13]; wp.p[7] = W[15]; wp.p[8] = W[18]; wp.p[9] = W[20];
        wp.p[10] = W[23]; wp.p[11] = W[25];
        k_cvt_w<<<(131072 / 4 + 255) / 256, 256>>>(wp);
    }

    // CSR build
    cudaMemsetAsync(degp, 0, NN * sizeof(int));
    k_count<<<(EE / 4 + 255) / 256, 256>>>(ei);
    k_scan<<<1, 1024>>>();
    k_fill<<<(EE / 4 + 255) / 256, 256>>>(ei);

    const int SPMM_BLOCKS_1 = (NN + 7) / 8;    // warp per node, 8 warps/block
    const int SPMM_BLOCKS_2 = (NN + 15) / 16;  // 2 nodes/warp
    dim3 gg((NN + 127) / 128, 2);

    float* wtfm = wtf;
    float* wtfv = wtf + 65536;

    // layer 0
    k_spmm0<<<SPMM_BLOCKS_2, 256>>>(x);
    {
        GArgs am = {agg, xtf, wtfm + 0, wtfm + 8192, W[1], W[3], W[4], h1m};
        GArgs av = {agg, xtf, wtfv + 0, wtfv + 8192, W[14], W[16], W[17], h1v};
        k_gemm_tc<64, 0><<<gg, 256, SMEM>>>(am, av);
    }
    // layer 1
    k_spmm1d<<<SPMM_BLOCKS_1, 256>>>(h1m, h1v);
    {
        GArgs am = {agg, h1m, wtfm + 16384, wtfm + 32768, W[6], W[8], W[9], h2m};
        GArgs av = {aggv, h1v, wtfv + 16384, wtfv + 32768, W[19], W[21], W[22], h2v};
        k_gemm_tc<128, 0><<<gg, 256, SMEM>>>(am, av);
    }
    // layer 2: PR = [h2@Wl^T | h2@Wr^T + bl], then out = S*P + R
    {
        GArgs am = {h2m, nullptr, wtfm + 49152, nullptr, W[11], nullptr, nullptr, agg};
        GArgs av = {h2v, nullptr, wtfv + 49152, nullptr, W[24], nullptr, nullptr, aggv};
        k_gemm_tc<128, 1><<<gg, 256, SMEM>>>(am, av);
    }
    k_spmm2d<<<SPMM_BLOCKS_2, 256>>>(agg, aggv, out_mu, out_lv);
}